// round 2
// baseline (speedup 1.0000x reference)
#include <cuda_runtime.h>

// Dense 3D convolution, stride 1, pad 1, K=3.
// x: [2, 32, 32, 96, 96] f32   (N, IC, D, H, W)
// w: [64, 32, 3, 3, 3]   f32   (OC, IC, KD, KH, KW)
// b: [64] f32
// y: [2, 64, 32, 96, 96] f32

#define NB 2
#define IC 32
#define OC 64
#define DD 32
#define HH 96
#define WW 96

#define W_T 32
#define H_T 4

#define IN_TILE (3 * (H_T + 2) * (W_T + 2))   // 612
#define W_TILE  (OC * 27)                     // 1728

__global__ __launch_bounds__(256, 2)
void conv3d_direct_kernel(const float* __restrict__ x,
                          const float* __restrict__ w,
                          const float* __restrict__ bias,
                          float* __restrict__ y)
{
    __shared__ float s_in[3][H_T + 2][W_T + 2];   // [kd][h][w] halo tile, one ic
    __shared__ float s_w[OC * 27];                // [oc][k] flat, one ic

    const int t  = threadIdx.x;
    const int tx = t & 31;          // output w lane
    const int ty = t >> 5;          // 0..7 -> oc group (warp-uniform)

    const int bx = blockIdx.x;      // 0..71 = (W/32=3) * (H/4=24)
    const int w0 = (bx % (WW / W_T)) * W_T;
    const int h0 = (bx / (WW / W_T)) * H_T;
    const int d  = blockIdx.y;
    const int n  = blockIdx.z;

    float acc[8][H_T];
    #pragma unroll
    for (int i = 0; i < 8; i++)
        #pragma unroll
        for (int j = 0; j < H_T; j++) acc[i][j] = 0.f;

    const float* xn = x + (size_t)n * IC * DD * HH * WW;

    for (int ic = 0; ic < IC; ++ic) {
        // ---- cooperative input halo load (612 f32, zero-padded) ----
        const float* xp = xn + (size_t)ic * DD * HH * WW;
        for (int i = t; i < IN_TILE; i += 256) {
            const int kd = i / ((H_T + 2) * (W_T + 2));
            const int r  = i % ((H_T + 2) * (W_T + 2));
            const int hh = r / (W_T + 2);
            const int ww = r % (W_T + 2);
            const int gd = d + kd - 1;
            const int gh = h0 + hh - 1;
            const int gw = w0 + ww - 1;
            float v = 0.f;
            if (gd >= 0 && gd < DD && gh >= 0 && gh < HH && gw >= 0 && gw < WW)
                v = xp[(gd * HH + gh) * WW + gw];
            (&s_in[0][0][0])[i] = v;
        }
        // ---- cooperative weight load (1728 f32, coalesced) ----
        // s_w[oc*27 + k] = w[oc*IC*27 + ic*27 + k]
        for (int i = t; i < W_TILE; i += 256) {
            const int oc = i / 27;
            const int k  = i - oc * 27;
            s_w[i] = w[oc * (IC * 27) + ic * 27 + k];
        }
        __syncthreads();

        // ---- compute: kd outer so the register input cache stays small ----
        #pragma unroll
        for (int kd = 0; kd < 3; kd++) {
            // register cache of this thread's input footprint for this kd:
            // rows h0-1 .. h0+4 (6), cols tx .. tx+2 (3)
            float rin[H_T + 2][3];
            #pragma unroll
            for (int hh = 0; hh < H_T + 2; hh++)
                #pragma unroll
                for (int kw = 0; kw < 3; kw++)
                    rin[hh][kw] = s_in[kd][hh][tx + kw];

            #pragma unroll
            for (int oi = 0; oi < 8; oi++) {
                const float* wp = &s_w[(ty * 8 + oi) * 27 + kd * 9];
                #pragma unroll
                for (int kh = 0; kh < 3; kh++) {
                    #pragma unroll
                    for (int kw = 0; kw < 3; kw++) {
                        const float wv = wp[kh * 3 + kw];   // warp-uniform LDS
                        #pragma unroll
                        for (int h = 0; h < H_T; h++)
                            acc[oi][h] += wv * rin[kh + h][kw];
                    }
                }
            }
        }
        __syncthreads();
    }

    // ---- epilogue ----
    #pragma unroll
    for (int oi = 0; oi < 8; oi++) {
        const int oc = ty * 8 + oi;
        const float b = bias[oc];
        float* yp = y + (((size_t)n * OC + oc) * DD + d) * (HH * WW);
        #pragma unroll
        for (int h = 0; h < H_T; h++)
            yp[(h0 + h) * WW + w0 + tx] = acc[oi][h] + b;
    }
}

extern "C" void kernel_launch(void* const* d_in, const int* in_sizes, int n_in,
                              void* d_out, int out_size)
{
    const float* x    = (const float*)d_in[0];
    const float* wgt  = (const float*)d_in[1];
    const float* bias = (const float*)d_in[2];
    float* y = (float*)d_out;

    dim3 grid((WW / W_T) * (HH / H_T), DD, NB);   // (72, 32, 2)
    conv3d_direct_kernel<<<grid, 256>>>(x, wgt, bias, y);
}

// round 3
// speedup vs baseline: 1.0022x; 1.0022x over previous
#include <cuda_runtime.h>

// Dense 3D convolution, stride 1, pad 1, K=3.
// x: [2, 32, 32, 96, 96] f32   (N, IC, D, H, W)
// w: [64, 32, 3, 3, 3]   f32   (OC, IC, KD, KH, KW)
// b: [64] f32
// y: [2, 64, 32, 96, 96] f32

#define NB 2
#define IC 32
#define OC 64
#define DD 32
#define HH 96
#define WW 96

#define W_T 32
#define H_T 4

#define IN_TILE (3 * (H_T + 2) * (W_T + 2))   // 612
#define W_TILE  (OC * 27)                     // 1728

__global__ __launch_bounds__(256, 2)
void conv3d_direct_kernel(const float* __restrict__ x,
                          const float* __restrict__ w,
                          const float* __restrict__ bias,
                          float* __restrict__ y)
{
    __shared__ float s_in[3][H_T + 2][W_T + 2];   // [kd][h][w] halo tile, one ic
    __shared__ float s_w[OC * 27];                // [oc][k] flat, one ic

    const int t  = threadIdx.x;
    const int tx = t & 31;          // output w lane
    const int ty = t >> 5;          // 0..7 -> oc group (warp-uniform)

    const int bx = blockIdx.x;      // 0..71 = (W/32=3) * (H/4=24)
    const int w0 = (bx % (WW / W_T)) * W_T;
    const int h0 = (bx / (WW / W_T)) * H_T;
    const int d  = blockIdx.y;
    const int n  = blockIdx.z;

    float acc[8][H_T];
    #pragma unroll
    for (int i = 0; i < 8; i++)
        #pragma unroll
        for (int j = 0; j < H_T; j++) acc[i][j] = 0.f;

    const float* xn = x + (size_t)n * IC * DD * HH * WW;

    for (int ic = 0; ic < IC; ++ic) {
        // ---- cooperative input halo load (612 f32, zero-padded) ----
        const float* xp = xn + (size_t)ic * DD * HH * WW;
        for (int i = t; i < IN_TILE; i += 256) {
            const int kd = i / ((H_T + 2) * (W_T + 2));
            const int r  = i % ((H_T + 2) * (W_T + 2));
            const int hh = r / (W_T + 2);
            const int ww = r % (W_T + 2);
            const int gd = d + kd - 1;
            const int gh = h0 + hh - 1;
            const int gw = w0 + ww - 1;
            float v = 0.f;
            if (gd >= 0 && gd < DD && gh >= 0 && gh < HH && gw >= 0 && gw < WW)
                v = xp[(gd * HH + gh) * WW + gw];
            (&s_in[0][0][0])[i] = v;
        }
        // ---- cooperative weight load (1728 f32, coalesced) ----
        // s_w[oc*27 + k] = w[oc*IC*27 + ic*27 + k]
        for (int i = t; i < W_TILE; i += 256) {
            const int oc = i / 27;
            const int k  = i - oc * 27;
            s_w[i] = w[oc * (IC * 27) + ic * 27 + k];
        }
        __syncthreads();

        // ---- compute: kd outer so the register input cache stays small ----
        #pragma unroll
        for (int kd = 0; kd < 3; kd++) {
            // register cache of this thread's input footprint for this kd:
            // rows h0-1 .. h0+4 (6), cols tx .. tx+2 (3)
            float rin[H_T + 2][3];
            #pragma unroll
            for (int hh = 0; hh < H_T + 2; hh++)
                #pragma unroll
                for (int kw = 0; kw < 3; kw++)
                    rin[hh][kw] = s_in[kd][hh][tx + kw];

            #pragma unroll
            for (int oi = 0; oi < 8; oi++) {
                const float* wp = &s_w[(ty * 8 + oi) * 27 + kd * 9];
                #pragma unroll
                for (int kh = 0; kh < 3; kh++) {
                    #pragma unroll
                    for (int kw = 0; kw < 3; kw++) {
                        const float wv = wp[kh * 3 + kw];   // warp-uniform LDS
                        #pragma unroll
                        for (int h = 0; h < H_T; h++)
                            acc[oi][h] += wv * rin[kh + h][kw];
                    }
                }
            }
        }
        __syncthreads();
    }

    // ---- epilogue ----
    #pragma unroll
    for (int oi = 0; oi < 8; oi++) {
        const int oc = ty * 8 + oi;
        const float b = bias[oc];
        float* yp = y + (((size_t)n * OC + oc) * DD + d) * (HH * WW);
        #pragma unroll
        for (int h = 0; h < H_T; h++)
            yp[(h0 + h) * WW + w0 + tx] = acc[oi][h] + b;
    }
}

extern "C" void kernel_launch(void* const* d_in, const int* in_sizes, int n_in,
                              void* d_out, int out_size)
{
    const float* x    = (const float*)d_in[0];
    const float* wgt  = (const float*)d_in[1];
    const float* bias = (const float*)d_in[2];
    float* y = (float*)d_out;

    dim3 grid((WW / W_T) * (HH / H_T), DD, NB);   // (72, 32, 2)
    conv3d_direct_kernel<<<grid, 256>>>(x, wgt, bias, y);
}

// round 5
// speedup vs baseline: 2.9679x; 2.9613x over previous
#include <cuda_runtime.h>
#include <cuda_bf16.h>
#include <cstdint>

// Dense 3D conv (stride1, pad1, K=3) as 9 kw-fused shifted GEMMs on mma.sync bf16.
// x:[2,32,32,96,96] f32  w:[64,32,3,3,3] f32  b:[64]  y:[2,64,32,96,96] f32
//
// E: channels-last padded bf16 split  [70 planes][98*98 pos][hi(32ic)|lo(32ic)]
// Wm: [9 (kd,kh)][3 kw][64 oc][120 k]  k = [whi(32) | whi(32) | wlo(32) | zero(24)]
// fp32 via y = x_hi*w_hi + x_lo*w_hi + x_hi*w_lo  (drops lo*lo ~ 2^-16 rel)

#define PW 98
#define PPLANE (PW*PW)          // 9604
#define PLANES 70               // guard | n0: 34 | n1: 34 | guard
#define GRPS 76                 // ceil(9604/128)
#define APITCH 144              // 128B data + 16B pad (conflict-free ldmatrix)
#define BPITCH 240              // 120 bf16 per row (conflict-free ldmatrix)
#define ABUF (130*APITCH)       // 18720
#define BBUF (3*64*BPITCH)      // 46080
#define SMEM_REQ (2*ABUF + 2*BBUF + 128)   // 129728

__device__ __align__(128) __nv_bfloat16 g_E[(size_t)PLANES * PPLANE * 64];  // ~86 MB
__device__ __align__(128) __nv_bfloat16 g_Wm[9 * 3 * 64 * 120];             // 405 KB

// ---------------- helpers --------------------------------------------------
__device__ __forceinline__ uint32_t smem_u32(const void* p) {
    uint32_t a;
    asm("{ .reg .u64 t; cvta.to.shared.u64 t, %1; cvt.u32.u64 %0, t; }" : "=r"(a) : "l"(p));
    return a;
}
#define CP_ASYNC16(dst, src) \
    asm volatile("cp.async.cg.shared.global [%0], [%1], 16;" :: "r"(dst), "l"(src) : "memory")
#define CP_COMMIT() asm volatile("cp.async.commit_group;" ::: "memory")

#define LDMX4(r, addr) \
    asm volatile("ldmatrix.sync.aligned.m8n8.x4.shared.b16 {%0,%1,%2,%3}, [%4];" \
        : "=r"((r)[0]), "=r"((r)[1]), "=r"((r)[2]), "=r"((r)[3]) : "r"(addr))

#define MMA16816(d, a, b0, b1) \
    asm volatile("mma.sync.aligned.m16n8k16.row.col.f32.bf16.bf16.f32 " \
        "{%0,%1,%2,%3}, {%4,%5,%6,%7}, {%8,%9}, {%0,%1,%2,%3};" \
        : "+f"((d)[0]), "+f"((d)[1]), "+f"((d)[2]), "+f"((d)[3]) \
        : "r"((a)[0]), "r"((a)[1]), "r"((a)[2]), "r"((a)[3]), "r"(b0), "r"(b1))

// ---------------- prep: E (bf16 hi/lo split, fully padded) -----------------
__global__ __launch_bounds__(256) void prep_e_kernel(const float* __restrict__ x) {
    __shared__ float sx[32][96];
    const int bx = blockIdx.x;
    const int hp = bx % PW;
    const int pd = (bx / PW) % 34;
    const int n  = bx / (PW * 34);
    const int t  = threadIdx.x;
    const bool rv = (pd >= 1 && pd <= 32 && hp >= 1 && hp <= 96);
    if (rv) {
        const int d = pd - 1, h = hp - 1;
        for (int i = t; i < 32 * 96; i += 256) {
            const int ic = i / 96, w = i % 96;
            sx[ic][w] = x[((((size_t)n * 32 + ic) * 32 + d) * 96 + h) * 96 + w];
        }
    }
    __syncthreads();
    __nv_bfloat16* row = g_E + ((size_t)(1 + n * 34 + pd) * PPLANE + (size_t)hp * PW) * 64;
    for (int i = t; i < PW * 64; i += 256) {
        const int wp = i >> 6, c = i & 63, ic = c & 31;
        float v = 0.f;
        if (rv && wp >= 1 && wp <= 96) v = sx[ic][wp - 1];
        const __nv_bfloat16 hv = __float2bfloat16(v);
        row[i] = (c < 32) ? hv : __float2bfloat16(v - __bfloat162float(hv));
    }
}

// ---------------- prep: Wm -------------------------------------------------
__global__ __launch_bounds__(256) void prep_w_kernel(const float* __restrict__ w) {
    const int i = blockIdx.x * 256 + threadIdx.x;
    if (i >= 9 * 3 * 64 * 120) return;
    const int k  = i % 120;
    const int oc = (i / 120) & 63;
    const int kw = (i / (120 * 64)) % 3;
    const int st = i / (120 * 64 * 3);
    const int kd = st / 3, kh = st % 3;
    const int s27 = kd * 9 + kh * 3 + kw;
    const int ic = k & 31;
    const float wv = w[(oc * 32 + ic) * 27 + s27];
    const __nv_bfloat16 hi = __float2bfloat16(wv);
    __nv_bfloat16 val;
    if (k < 64)       val = hi;
    else if (k < 96)  val = __float2bfloat16(wv - __bfloat162float(hi));
    else              val = __float2bfloat16(0.f);
    g_Wm[i] = val;
}

// ---------------- main -----------------------------------------------------
__global__ __launch_bounds__(256, 1)
void conv_mma_kernel(const float* __restrict__ bias, float* __restrict__ y)
{
    extern __shared__ __align__(128) char smem[];
    __shared__ float sbias[64];

    const int t = threadIdx.x, lane = t & 31, wid = t >> 5;
    const int wm = wid & 3, wn = wid >> 2;     // 4 M-warps x 2 N-warps
    const int gid = lane >> 2, tig = lane & 3;

    uint32_t sb = smem_u32(smem);
    sb = (sb + 127u) & ~127u;

    const int g   = blockIdx.x;
    const int grp = g % GRPS;
    const int d   = (g / GRPS) % 32;
    const int n   = g / (GRPS * 32);
    const long long row0 = (long long)(n * 34 + d + 2) * PPLANE + (long long)grp * 128;

    if (t < 64) sbias[t] = bias[t];

    float acc[2][4][4];
    #pragma unroll
    for (int a = 0; a < 2; a++)
        #pragma unroll
        for (int b = 0; b < 4; b++)
            #pragma unroll
            for (int c = 0; c < 4; c++) acc[a][b][c] = 0.f;

    auto docopy = [&](int st, int b) {
        const int kd = st / 3, kh = st % 3;
        const char* srcA = (const char*)g_E +
            (size_t)((row0 + (long long)(kd - 1) * PPLANE + (long long)(kh - 1) * PW - 1) * 128);
        const uint32_t ab = sb + b * ABUF;
        for (int i = t; i < 130 * 8; i += 256)
            CP_ASYNC16(ab + (i >> 3) * APITCH + (i & 7) * 16, srcA + (size_t)i * 16);
        const char* srcB = (const char*)g_Wm + (size_t)st * 3 * 64 * BPITCH;
        const uint32_t bb = sb + 2 * ABUF + b * BBUF;
        for (int i = t; i < BBUF / 16; i += 256)
            CP_ASYNC16(bb + i * 16, srcB + (size_t)i * 16);
        CP_COMMIT();
    };

    docopy(0, 0);
    docopy(1, 1);

    // ldmatrix per-lane row/k-half selectors
    const uint32_t a_lr = (lane & 7) + ((lane >> 3) & 1) * 8;   // A: mats (m0-7,k0-7)(m8-15,k0-7)(m0-7,k8-15)(m8-15,k8-15)
    const uint32_t a_kh = ((lane >> 4) & 1) * 16;
    const uint32_t b_lr = (lane & 7) + ((lane >> 4) & 1) * 8;   // B: mats (n0-7,k0-7)(n0-7,k8-15)(n8-15,k0-7)(n8-15,k8-15)
    const uint32_t b_kh = ((lane >> 3) & 1) * 16;

    for (int st = 0; st < 9; st++) {
        const int b = st & 1;
        if (st < 8) asm volatile("cp.async.wait_group 1;" ::: "memory");
        else        asm volatile("cp.async.wait_group 0;" ::: "memory");
        __syncthreads();

        const uint32_t ab = sb + b * ABUF;
        const uint32_t bb = sb + 2 * ABUF + b * BBUF;

        #pragma unroll
        for (int kw = 0; kw < 3; kw++) {
            const uint32_t a0addr = ab + (wm * 32 + kw + a_lr) * APITCH + a_kh;
            const uint32_t b0addr = bb + (kw * 64 + wn * 32 + b_lr) * BPITCH + b_kh;
            #pragma unroll
            for (int s = 0; s < 6; s++) {
                const uint32_t ka = (uint32_t)((s < 4 ? s : s - 4) * 32);
                const uint32_t kb = (uint32_t)(s * 32);
                uint32_t A0[4], A1[4], B0[4], B1[4];
                LDMX4(A0, a0addr + ka);
                LDMX4(A1, a0addr + 16 * APITCH + ka);
                LDMX4(B0, b0addr + kb);
                LDMX4(B1, b0addr + 16 * BPITCH + kb);
                MMA16816(acc[0][0], A0, B0[0], B0[1]);
                MMA16816(acc[0][1], A0, B0[2], B0[3]);
                MMA16816(acc[0][2], A0, B1[0], B1[1]);
                MMA16816(acc[0][3], A0, B1[2], B1[3]);
                MMA16816(acc[1][0], A1, B0[0], B0[1]);
                MMA16816(acc[1][1], A1, B0[2], B0[3]);
                MMA16816(acc[1][2], A1, B1[0], B1[1]);
                MMA16816(acc[1][3], A1, B1[2], B1[3]);
            }
        }
        __syncthreads();
        if (st + 2 < 9) docopy(st + 2, b);
    }

    // ---------------- epilogue ----------------
    #pragma unroll
    for (int mt = 0; mt < 2; mt++) {
        #pragma unroll
        for (int hf = 0; hf < 2; hf++) {
            const int pos = grp * 128 + wm * 32 + mt * 16 + gid + hf * 8;
            const int hp = pos / PW, wp = pos % PW;
            if (pos >= PPLANE || hp < 1 || hp > 96 || wp < 1 || wp > 96) continue;
            float* yp = y + ((size_t)(n * 64) * 32 + d) * 9216
                          + (size_t)(hp - 1) * 96 + (wp - 1);
            #pragma unroll
            for (int nt = 0; nt < 4; nt++) {
                const int oc = wn * 32 + nt * 8 + tig * 2;
                yp[(size_t)oc * 32 * 9216]       = acc[mt][nt][hf * 2 + 0] + sbias[oc];
                yp[(size_t)(oc + 1) * 32 * 9216] = acc[mt][nt][hf * 2 + 1] + sbias[oc + 1];
            }
        }
    }
}

extern "C" void kernel_launch(void* const* d_in, const int* in_sizes, int n_in,
                              void* d_out, int out_size)
{
    const float* x    = (const float*)d_in[0];
    const float* wgt  = (const float*)d_in[1];
    const float* bias = (const float*)d_in[2];
    float* y = (float*)d_out;

    cudaFuncSetAttribute(conv_mma_kernel, cudaFuncAttributeMaxDynamicSharedMemorySize, SMEM_REQ);

    prep_w_kernel<<<(9 * 3 * 64 * 120 + 255) / 256, 256>>>(wgt);
    prep_e_kernel<<<2 * 34 * PW, 256>>>(x);
    conv_mma_kernel<<<2 * 32 * GRPS, 256, SMEM_REQ>>>(bias, y);
}

// round 6
// speedup vs baseline: 4.1105x; 1.3850x over previous
#include <cuda_runtime.h>
#include <cuda_fp16.h>
#include <cstdint>

// Dense 3D conv (stride1, pad1, K=3) as 9 kw-fused shifted GEMMs on mma.sync fp16.
// x:[2,32,32,96,96] f32  w:[64,32,3,3,3] f32  b:[64]  y:[2,64,32,96,96] f32
//
// E: channels-last padded fp16 split  [70 planes][98*98 pos][hi(32ic)|lo(32ic)]
// Wm: [9 (kd,kh)][3 kw][64 oc][64 k]   k = [whi(32) | whi(32)]   (whi = fp16(w))
// fp32 via y = (x_hi + x_lo) * w_hi   (fp16: drops x*(w-whi) ~ 2^-12.8 RMS rel)

#define PW 98
#define PPLANE (PW*PW)          // 9604
#define PLANES 70               // guard | n0: 34 | n1: 34 | guard
#define GRPS 76                 // ceil(9604/128)
#define APITCH 144              // 128B data + 16B pad (conflict-free ldmatrix)
#define BPITCH 144              // 64 fp16 + 16B pad (stride 36 words: conflict-free)
#define ABUF (130*APITCH)       // 18720
#define BBUF (3*64*BPITCH)      // 27648
#define SMEM_REQ (2*ABUF + 2*BBUF + 128)   // 92864

__device__ __align__(128) __half g_E[(size_t)PLANES * PPLANE * 64];   // ~86 MB
__device__ __align__(128) __half g_Wm[9 * 3 * 64 * 64];               // 216 KB

// ---------------- helpers --------------------------------------------------
__device__ __forceinline__ uint32_t smem_u32(const void* p) {
    uint32_t a;
    asm("{ .reg .u64 t; cvta.to.shared.u64 t, %1; cvt.u32.u64 %0, t; }" : "=r"(a) : "l"(p));
    return a;
}
#define CP_ASYNC16(dst, src) \
    asm volatile("cp.async.cg.shared.global [%0], [%1], 16;" :: "r"(dst), "l"(src) : "memory")
#define CP_COMMIT() asm volatile("cp.async.commit_group;" ::: "memory")

#define LDMX4(r, addr) \
    asm volatile("ldmatrix.sync.aligned.m8n8.x4.shared.b16 {%0,%1,%2,%3}, [%4];" \
        : "=r"((r)[0]), "=r"((r)[1]), "=r"((r)[2]), "=r"((r)[3]) : "r"(addr))

#define MMA16816(d, a, b0, b1) \
    asm volatile("mma.sync.aligned.m16n8k16.row.col.f32.f16.f16.f32 " \
        "{%0,%1,%2,%3}, {%4,%5,%6,%7}, {%8,%9}, {%0,%1,%2,%3};" \
        : "+f"((d)[0]), "+f"((d)[1]), "+f"((d)[2]), "+f"((d)[3]) \
        : "r"((a)[0]), "r"((a)[1]), "r"((a)[2]), "r"((a)[3]), "r"(b0), "r"(b1))

// ---------------- prep: E (fp16 hi/lo split, fully padded) -----------------
__global__ __launch_bounds__(256) void prep_e_kernel(const float* __restrict__ x) {
    __shared__ float sx[32][96];
    const int bx = blockIdx.x;
    const int hp = bx % PW;
    const int pd = (bx / PW) % 34;
    const int n  = bx / (PW * 34);
    const int t  = threadIdx.x;
    const bool rv = (pd >= 1 && pd <= 32 && hp >= 1 && hp <= 96);
    if (rv) {
        const int d = pd - 1, h = hp - 1;
        for (int i = t; i < 32 * 96; i += 256) {
            const int ic = i / 96, w = i % 96;
            sx[ic][w] = x[((((size_t)n * 32 + ic) * 32 + d) * 96 + h) * 96 + w];
        }
    }
    __syncthreads();
    __half* row = g_E + ((size_t)(1 + n * 34 + pd) * PPLANE + (size_t)hp * PW) * 64;
    for (int i = t; i < PW * 64; i += 256) {
        const int wp = i >> 6, c = i & 63, ic = c & 31;
        float v = 0.f;
        if (rv && wp >= 1 && wp <= 96) v = sx[ic][wp - 1];
        const __half hv = __float2half_rn(v);
        row[i] = (c < 32) ? hv : __float2half_rn(v - __half2float(hv));
    }
}

// ---------------- prep: Wm -------------------------------------------------
__global__ __launch_bounds__(256) void prep_w_kernel(const float* __restrict__ w) {
    const int i = blockIdx.x * 256 + threadIdx.x;
    if (i >= 9 * 3 * 64 * 64) return;
    const int k  = i & 63;
    const int oc = (i >> 6) & 63;
    const int kw = (i >> 12) % 3;
    const int st = i / (64 * 64 * 3);
    const int kd = st / 3, kh = st % 3;
    const int s27 = kd * 9 + kh * 3 + kw;
    const int ic = k & 31;
    g_Wm[i] = __float2half_rn(w[(oc * 32 + ic) * 27 + s27]);
}

// ---------------- main -----------------------------------------------------
__global__ __launch_bounds__(256, 1)
void conv_mma_kernel(const float* __restrict__ bias, float* __restrict__ y)
{
    extern __shared__ __align__(128) char smem[];
    __shared__ float sbias[64];

    const int t = threadIdx.x, lane = t & 31, wid = t >> 5;
    const int wm = wid & 3, wn = wid >> 2;     // 4 M-warps x 2 N-warps
    const int gid = lane >> 2, tig = lane & 3;

    uint32_t sb = smem_u32(smem);
    sb = (sb + 127u) & ~127u;

    const int g   = blockIdx.x;
    const int grp = g % GRPS;
    const int d   = (g / GRPS) % 32;
    const int n   = g / (GRPS * 32);
    const long long row0 = (long long)(n * 34 + d + 2) * PPLANE + (long long)grp * 128;

    if (t < 64) sbias[t] = bias[t];

    float acc[2][4][4];
    #pragma unroll
    for (int a = 0; a < 2; a++)
        #pragma unroll
        for (int b = 0; b < 4; b++)
            #pragma unroll
            for (int c = 0; c < 4; c++) acc[a][b][c] = 0.f;

    auto docopy = [&](int st, int b) {
        const int kd = st / 3, kh = st % 3;
        const char* srcA = (const char*)g_E +
            (size_t)((row0 + (long long)(kd - 1) * PPLANE + (long long)(kh - 1) * PW - 1) * 128);
        const uint32_t ab = sb + b * ABUF;
        for (int i = t; i < 130 * 8; i += 256)
            CP_ASYNC16(ab + (i >> 3) * APITCH + (i & 7) * 16, srcA + (size_t)i * 16);
        const char* srcB = (const char*)g_Wm + (size_t)st * 3 * 64 * 128;
        const uint32_t bb = sb + 2 * ABUF + b * BBUF;
        for (int i = t; i < 3 * 64 * 8; i += 256)
            CP_ASYNC16(bb + (i >> 3) * BPITCH + (i & 7) * 16, srcB + (size_t)i * 16);
        CP_COMMIT();
    };

    docopy(0, 0);
    docopy(1, 1);

    // ldmatrix per-lane row/k-half selectors
    const uint32_t a_lr = (lane & 7) + ((lane >> 3) & 1) * 8;   // A row within 16
    const uint32_t a_kh = ((lane >> 4) & 1) * 16;               // A k-half (bytes)
    const uint32_t b_lr = (lane & 7) + ((lane >> 4) & 1) * 8;   // B row within 16
    const uint32_t b_kh = ((lane >> 3) & 1) * 16;               // B k-half (bytes)

    for (int st = 0; st < 9; st++) {
        const int b = st & 1;
        if (st < 8) asm volatile("cp.async.wait_group 1;" ::: "memory");
        else        asm volatile("cp.async.wait_group 0;" ::: "memory");
        __syncthreads();

        const uint32_t ab = sb + b * ABUF;
        const uint32_t bb = sb + 2 * ABUF + b * BBUF;

        #pragma unroll
        for (int kw = 0; kw < 3; kw++) {
            const uint32_t a0addr = ab + (wm * 32 + kw + a_lr) * APITCH + a_kh;
            const uint32_t b0addr = bb + (kw * 64 + wn * 32 + b_lr) * BPITCH + b_kh;
            #pragma unroll
            for (int s = 0; s < 4; s++) {
                const uint32_t koff = (uint32_t)(s * 32);   // bytes: k16 block s
                uint32_t A0[4], A1[4], B0[4], B1[4];
                LDMX4(A0, a0addr + koff);
                LDMX4(A1, a0addr + 16 * APITCH + koff);
                LDMX4(B0, b0addr + koff);
                LDMX4(B1, b0addr + 16 * BPITCH + koff);
                MMA16816(acc[0][0], A0, B0[0], B0[1]);
                MMA16816(acc[0][1], A0, B0[2], B0[3]);
                MMA16816(acc[0][2], A0, B1[0], B1[1]);
                MMA16816(acc[0][3], A0, B1[2], B1[3]);
                MMA16816(acc[1][0], A1, B0[0], B0[1]);
                MMA16816(acc[1][1], A1, B0[2], B0[3]);
                MMA16816(acc[1][2], A1, B1[0], B1[1]);
                MMA16816(acc[1][3], A1, B1[2], B1[3]);
            }
        }
        __syncthreads();
        if (st + 2 < 9) docopy(st + 2, b);
    }

    // ---------------- epilogue ----------------
    #pragma unroll
    for (int mt = 0; mt < 2; mt++) {
        #pragma unroll
        for (int hf = 0; hf < 2; hf++) {
            const int pos = grp * 128 + wm * 32 + mt * 16 + gid + hf * 8;
            const int hp = pos / PW, wp = pos % PW;
            if (pos >= PPLANE || hp < 1 || hp > 96 || wp < 1 || wp > 96) continue;
            float* yp = y + ((size_t)(n * 64) * 32 + d) * 9216
                          + (size_t)(hp - 1) * 96 + (wp - 1);
            #pragma unroll
            for (int nt = 0; nt < 4; nt++) {
                const int oc = wn * 32 + nt * 8 + tig * 2;
                yp[(size_t)oc * 32 * 9216]       = acc[mt][nt][hf * 2 + 0] + sbias[oc];
                yp[(size_t)(oc + 1) * 32 * 9216] = acc[mt][nt][hf * 2 + 1] + sbias[oc + 1];
            }
        }
    }
}

extern "C" void kernel_launch(void* const* d_in, const int* in_sizes, int n_in,
                              void* d_out, int out_size)
{
    const float* x    = (const float*)d_in[0];
    const float* wgt  = (const float*)d_in[1];
    const float* bias = (const float*)d_in[2];
    float* y = (float*)d_out;

    cudaFuncSetAttribute(conv_mma_kernel, cudaFuncAttributeMaxDynamicSharedMemorySize, SMEM_REQ);

    prep_w_kernel<<<(9 * 3 * 64 * 64 + 255) / 256, 256>>>(wgt);
    prep_e_kernel<<<2 * 34 * PW, 256>>>(x);
    conv_mma_kernel<<<2 * 32 * GRPS, 256, SMEM_REQ>>>(bias, y);
}

// round 7
// speedup vs baseline: 6.8218x; 1.6596x over previous
#include <cuda_runtime.h>
#include <cuda_fp16.h>
#include <cstdint>

// Dense 3D conv (stride1, pad1, K=3) as 9 kw-fused shifted GEMMs on mma.sync fp16.
// Pure fp16 operands (1-term): y = fp16(x) * fp16(w), fp32 accum.
// x:[2,32,32,96,96] f32  w:[64,32,3,3,3] f32  b:[64]  y:[2,64,32,96,96] f32
//
// E: channels-last padded fp16  [70 planes][98*98 pos][32 ic]
// Wm: [9 (kd,kh)][3 kw][64 oc][32 k]

#define PW 98
#define PPLANE (PW*PW)          // 9604
#define PLANES 70               // guard | n0: 34 | n1: 34 | guard
#define GRPS 76                 // ceil(9604/128)
#define APITCH 80               // 64B data + 16B pad (stride 20 words: conflict-free)
#define BPITCH 80
#define ABUF (130*APITCH)       // 10400
#define BBUF (3*64*BPITCH)      // 15360
#define SMEM_REQ (2*ABUF + 2*BBUF + 128)   // 51648

__device__ __align__(128) __half g_E[(size_t)PLANES * PPLANE * 32];   // ~43 MB
__device__ __align__(128) __half g_Wm[9 * 3 * 64 * 32];               // 108 KB

// ---------------- helpers --------------------------------------------------
__device__ __forceinline__ uint32_t smem_u32(const void* p) {
    uint32_t a;
    asm("{ .reg .u64 t; cvta.to.shared.u64 t, %1; cvt.u32.u64 %0, t; }" : "=r"(a) : "l"(p));
    return a;
}
#define CP_ASYNC16(dst, src) \
    asm volatile("cp.async.cg.shared.global [%0], [%1], 16;" :: "r"(dst), "l"(src) : "memory")
#define CP_COMMIT() asm volatile("cp.async.commit_group;" ::: "memory")

#define LDMX4(r, addr) \
    asm volatile("ldmatrix.sync.aligned.m8n8.x4.shared.b16 {%0,%1,%2,%3}, [%4];" \
        : "=r"((r)[0]), "=r"((r)[1]), "=r"((r)[2]), "=r"((r)[3]) : "r"(addr))

#define MMA16816(d, a, b0, b1) \
    asm volatile("mma.sync.aligned.m16n8k16.row.col.f32.f16.f16.f32 " \
        "{%0,%1,%2,%3}, {%4,%5,%6,%7}, {%8,%9}, {%0,%1,%2,%3};" \
        : "+f"((d)[0]), "+f"((d)[1]), "+f"((d)[2]), "+f"((d)[3]) \
        : "r"((a)[0]), "r"((a)[1]), "r"((a)[2]), "r"((a)[3]), "r"(b0), "r"(b1))

// ---------------- prep: E (fp16, fully padded) ------------------------------
__global__ __launch_bounds__(256) void prep_e_kernel(const float* __restrict__ x) {
    __shared__ float sx[32][96];
    const int bx = blockIdx.x;
    const int hp = bx % PW;
    const int pd = (bx / PW) % 34;
    const int n  = bx / (PW * 34);
    const int t  = threadIdx.x;
    const bool rv = (pd >= 1 && pd <= 32 && hp >= 1 && hp <= 96);
    if (rv) {
        const int d = pd - 1, h = hp - 1;
        for (int i = t; i < 32 * 96; i += 256) {
            const int ic = i / 96, w = i % 96;
            sx[ic][w] = x[((((size_t)n * 32 + ic) * 32 + d) * 96 + h) * 96 + w];
        }
    }
    __syncthreads();
    __half* row = g_E + ((size_t)(1 + n * 34 + pd) * PPLANE + (size_t)hp * PW) * 32;
    for (int i = t; i < PW * 32; i += 256) {
        const int wp = i >> 5, ic = i & 31;
        float v = 0.f;
        if (rv && wp >= 1 && wp <= 96) v = sx[ic][wp - 1];
        row[i] = __float2half_rn(v);
    }
}

// ---------------- prep: Wm --------------------------------------------------
__global__ __launch_bounds__(256) void prep_w_kernel(const float* __restrict__ w) {
    const int i = blockIdx.x * 256 + threadIdx.x;
    if (i >= 9 * 3 * 64 * 32) return;
    const int ic = i & 31;
    const int oc = (i >> 5) & 63;
    const int kw = (i >> 11) % 3;
    const int st = i / (32 * 64 * 3);
    const int kd = st / 3, kh = st % 3;
    const int s27 = kd * 9 + kh * 3 + kw;
    g_Wm[i] = __float2half_rn(w[(oc * 32 + ic) * 27 + s27]);
}

// ---------------- main -------------------------------------------------------
__global__ __launch_bounds__(256, 2)
void conv_mma_kernel(const float* __restrict__ bias, float* __restrict__ y)
{
    extern __shared__ __align__(128) char smem[];
    __shared__ float sbias[64];

    const int t = threadIdx.x, lane = t & 31, wid = t >> 5;
    const int wm = wid & 3, wn = wid >> 2;     // 4 M-warps x 2 N-warps
    const int gid = lane >> 2, tig = lane & 3;

    uint32_t sb = smem_u32(smem);
    sb = (sb + 127u) & ~127u;

    const int g   = blockIdx.x;
    const int grp = g % GRPS;
    const int d   = (g / GRPS) % 32;
    const int n   = g / (GRPS * 32);
    const long long row0 = (long long)(n * 34 + d + 2) * PPLANE + (long long)grp * 128;

    if (t < 64) sbias[t] = bias[t];

    float acc[2][4][4];
    #pragma unroll
    for (int a = 0; a < 2; a++)
        #pragma unroll
        for (int b = 0; b < 4; b++)
            #pragma unroll
            for (int c = 0; c < 4; c++) acc[a][b][c] = 0.f;

    auto docopy = [&](int st, int b) {
        const int kd = st / 3, kh = st % 3;
        const char* srcA = (const char*)g_E +
            (size_t)((row0 + (long long)(kd - 1) * PPLANE + (long long)(kh - 1) * PW - 1) * 64);
        const uint32_t ab = sb + b * ABUF;
        for (int i = t; i < 130 * 4; i += 256)
            CP_ASYNC16(ab + (i >> 2) * APITCH + (i & 3) * 16, srcA + (size_t)i * 16);
        const char* srcB = (const char*)g_Wm + (size_t)st * 3 * 64 * 64;
        const uint32_t bb = sb + 2 * ABUF + b * BBUF;
        for (int i = t; i < 3 * 64 * 4; i += 256)
            CP_ASYNC16(bb + (i >> 2) * BPITCH + (i & 3) * 16, srcB + (size_t)i * 16);
        CP_COMMIT();
    };

    docopy(0, 0);
    docopy(1, 1);

    // ldmatrix per-lane row/k-half selectors
    const uint32_t a_lr = (lane & 7) + ((lane >> 3) & 1) * 8;   // A row within 16
    const uint32_t a_kh = ((lane >> 4) & 1) * 16;               // A k-half (bytes)
    const uint32_t b_lr = (lane & 7) + ((lane >> 4) & 1) * 8;   // B row within 16
    const uint32_t b_kh = ((lane >> 3) & 1) * 16;               // B k-half (bytes)

    for (int st = 0; st < 9; st++) {
        const int b = st & 1;
        if (st < 8) asm volatile("cp.async.wait_group 1;" ::: "memory");
        else        asm volatile("cp.async.wait_group 0;" ::: "memory");
        __syncthreads();

        const uint32_t ab = sb + b * ABUF;
        const uint32_t bb = sb + 2 * ABUF + b * BBUF;

        #pragma unroll
        for (int kw = 0; kw < 3; kw++) {
            const uint32_t a0addr = ab + (wm * 32 + kw + a_lr) * APITCH + a_kh;
            const uint32_t b0addr = bb + (kw * 64 + wn * 32 + b_lr) * BPITCH + b_kh;
            #pragma unroll
            for (int s = 0; s < 2; s++) {
                const uint32_t koff = (uint32_t)(s * 32);   // bytes: k16 block s
                uint32_t A0[4], A1[4], B0[4], B1[4];
                LDMX4(A0, a0addr + koff);
                LDMX4(A1, a0addr + 16 * APITCH + koff);
                LDMX4(B0, b0addr + koff);
                LDMX4(B1, b0addr + 16 * BPITCH + koff);
                MMA16816(acc[0][0], A0, B0[0], B0[1]);
                MMA16816(acc[0][1], A0, B0[2], B0[3]);
                MMA16816(acc[0][2], A0, B1[0], B1[1]);
                MMA16816(acc[0][3], A0, B1[2], B1[3]);
                MMA16816(acc[1][0], A1, B0[0], B0[1]);
                MMA16816(acc[1][1], A1, B0[2], B0[3]);
                MMA16816(acc[1][2], A1, B1[0], B1[1]);
                MMA16816(acc[1][3], A1, B1[2], B1[3]);
            }
        }
        __syncthreads();
        if (st + 2 < 9) docopy(st + 2, b);
    }

    // ---------------- epilogue ----------------
    #pragma unroll
    for (int mt = 0; mt < 2; mt++) {
        #pragma unroll
        for (int hf = 0; hf < 2; hf++) {
            const int pos = grp * 128 + wm * 32 + mt * 16 + gid + hf * 8;
            const int hp = pos / PW, wp = pos % PW;
            if (pos >= PPLANE || hp < 1 || hp > 96 || wp < 1 || wp > 96) continue;
            float* yp = y + ((size_t)(n * 64) * 32 + d) * 9216
                          + (size_t)(hp - 1) * 96 + (wp - 1);
            #pragma unroll
            for (int nt = 0; nt < 4; nt++) {
                const int oc = wn * 32 + nt * 8 + tig * 2;
                yp[(size_t)oc * 32 * 9216]       = acc[mt][nt][hf * 2 + 0] + sbias[oc];
                yp[(size_t)(oc + 1) * 32 * 9216] = acc[mt][nt][hf * 2 + 1] + sbias[oc + 1];
            }
        }
    }
}

extern "C" void kernel_launch(void* const* d_in, const int* in_sizes, int n_in,
                              void* d_out, int out_size)
{
    const float* x    = (const float*)d_in[0];
    const float* wgt  = (const float*)d_in[1];
    const float* bias = (const float*)d_in[2];
    float* y = (float*)d_out;

    cudaFuncSetAttribute(conv_mma_kernel, cudaFuncAttributeMaxDynamicSharedMemorySize, SMEM_REQ);

    prep_w_kernel<<<(9 * 3 * 64 * 32 + 255) / 256, 256>>>(wgt);
    prep_e_kernel<<<2 * 34 * PW, 256>>>(x);
    conv_mma_kernel<<<2 * 32 * GRPS, 256, SMEM_REQ>>>(bias, y);
}